// round 6
// baseline (speedup 1.0000x reference)
#include <cuda_runtime.h>
#include <math.h>

#define TPB 512
#define NWARP 16
#define NBLK 148
#define TOTWARP (NBLK*NWARP)   // 2368
#define NRAYS 8192
#define LDW2 132
#define HSTR 132
#define GSTRIDE 1760
#define W2T_FLOATS (128*LDW2)
#define WSOFF W2T_FLOATS
#define GOFF (W2T_FLOATS + 2056)
#define SMEM_BYTES ((GOFF + NWARP*GSTRIDE)*4)

#define O_D    0
#define O_SDF  128
#define O_H1   256
#define O_WB   1312
#define O_CDF  1440
#define O_DF   1572
#define O_SF   1588
#define O_DM   1604
#define O_AUX  1732

typedef unsigned long long ull;

__device__ __forceinline__ ull fma2(ull a, ull b, ull c){
    ull d;
    asm("fma.rn.f32x2 %0, %1, %2, %3;" : "=l"(d) : "l"(a), "l"(b), "l"(c));
    return d;
}
__device__ __forceinline__ float lo32(ull v){ return __uint_as_float((unsigned)v); }
__device__ __forceinline__ float hi32(ull v){ return __uint_as_float((unsigned)(v>>32)); }

__device__ __forceinline__ float sigf(float x){
    return 1.0f/(1.0f + __expf(-x));
}

// One 8-point SDF MLP batch for THIS warp's ray. Warp-private.
__device__ __forceinline__ void sdf_batch(
    float* __restrict__ G, const float* __restrict__ W2T,
    int din_off, int base, int sout_off, int lane,
    const float* c0, const float* c1, const float* b2v, const float* w3v,
    float b3v)
{
    float* gh1 = G + O_H1;
    #pragma unroll
    for (int pt=0; pt<8; pt++){
        float dv = G[din_off + base + pt];
        #pragma unroll
        for (int u=0; u<4; u++){
            gh1[pt*HSTR + lane + 32*u] = fmaxf(fmaf(dv, c1[u], c0[u]), 0.f);
        }
    }
    __syncwarp();

    ull acc[4][8];
    #pragma unroll
    for (int u=0; u<4; u++)
        #pragma unroll
        for (int p=0; p<8; p++)
            acc[u][p] = (ull)__float_as_uint(b2v[u]);

    const ulonglong2* w0 = (const ulonglong2*)(W2T + (lane      )*LDW2);
    const ulonglong2* w1 = (const ulonglong2*)(W2T + (lane + 32 )*LDW2);
    const ulonglong2* w2r= (const ulonglong2*)(W2T + (lane + 64 )*LDW2);
    const ulonglong2* w3r= (const ulonglong2*)(W2T + (lane + 96 )*LDW2);

    #pragma unroll 4
    for (int k4=0; k4<32; k4++){
        ulonglong2 wv[4];
        wv[0]=w0[k4]; wv[1]=w1[k4]; wv[2]=w2r[k4]; wv[3]=w3r[k4];
        #pragma unroll
        for (int hh=0; hh<2; hh++){
            ulonglong2 hv[4];
            #pragma unroll
            for (int i=0;i<4;i++)
                hv[i] = *(const ulonglong2*)(gh1 + (hh*4+i)*HSTR + k4*4);
            #pragma unroll
            for (int u=0; u<4; u++){
                #pragma unroll
                for (int i=0; i<4; i++){
                    int p = hh*4 + i;
                    acc[u][p] = fma2(wv[u].x, hv[i].x, acc[u][p]);
                    acc[u][p] = fma2(wv[u].y, hv[i].y, acc[u][p]);
                }
            }
        }
    }

    #pragma unroll
    for (int pt=0; pt<8; pt++){
        float t = 0.f;
        #pragma unroll
        for (int u=0; u<4; u++){
            float f = lo32(acc[u][pt]) + hi32(acc[u][pt]);
            t += fmaxf(f, 0.f) * w3v[u];
        }
        #pragma unroll
        for (int o=16;o;o>>=1) t += __shfl_down_sync(0xffffffffu, t, o);
        if (lane == 0) G[sout_off + base + pt] = t + b3v;
    }
    __syncwarp();
}

__global__ void __launch_bounds__(TPB,1) neus_kernel(
    const float* __restrict__ rays_o, const float* __restrict__ rays_d,
    const float* __restrict__ W1, const float* __restrict__ b1,
    const float* __restrict__ W2, const float* __restrict__ b2,
    const float* __restrict__ W3, const float* __restrict__ b3,
    const float* __restrict__ R1, const float* __restrict__ r1,
    const float* __restrict__ R2, const float* __restrict__ r2,
    const float* __restrict__ s_val, float* __restrict__ out)
{
    extern __shared__ float sm[];
    float* W2T = sm;
    float* WS  = sm + WSOFF;
    float* W1s = WS;         // 384
    float* b1s = WS+384;     // 128
    float* b2s = WS+512;     // 128
    float* W3s = WS+640;     // 128
    float* R1s = WS+768;     // 768
    float* r1s = WS+1536;    // 128
    float* F0  = WS+1664;    // 128 (R2 col 0)
    float* F1  = WS+1792;    // 128
    float* F2  = WS+1920;    // 128
    float* r2s = WS+2048;    // 3
    float* b3p = WS+2051;
    float* scp = WS+2052;

    const int tid  = threadIdx.x;
    const int w    = tid >> 5;
    const int lane = tid & 31;
    const unsigned FULL = 0xffffffffu;

    // ---- stage weights once per SM ----
    for (int idx=tid; idx<128*128; idx+=TPB){
        int k = idx >> 7, jj = idx & 127;
        W2T[jj*LDW2 + k] = W2[idx];
    }
    for (int idx=tid; idx<384; idx+=TPB) W1s[idx] = W1[idx];
    for (int idx=tid; idx<128; idx+=TPB){
        b1s[idx]=b1[idx]; b2s[idx]=b2[idx]; W3s[idx]=W3[idx]; r1s[idx]=r1[idx];
        F0[idx]=R2[3*idx]; F1[idx]=R2[3*idx+1]; F2[idx]=R2[3*idx+2];
    }
    for (int idx=tid; idx<768; idx+=TPB) R1s[idx] = R1[idx];
    if (tid < 3) r2s[tid] = r2[tid];
    if (tid == 0){ b3p[0] = b3[0]; scp[0] = s_val[0]*64.0f; }
    __syncthreads();

    float* G = sm + GOFF + w*GSTRIDE;
    const int gw = blockIdx.x*NWARP + w;

    for (int ri=0; ri<4; ri++){
        const int ray = gw + ri*TOTWARP;
        if (ray >= NRAYS) break;

        if (lane == 0){
            float oxl=rays_o[ray*3+0], oyl=rays_o[ray*3+1], ozl=rays_o[ray*3+2];
            float ddx=rays_d[ray*3+0], ddy=rays_d[ray*3+1], ddz=rays_d[ray*3+2];
            float nrm = sqrtf(ddx*ddx+ddy*ddy+ddz*ddz);
            G[O_AUX+0]=oxl; G[O_AUX+1]=oyl; G[O_AUX+2]=ozl;
            G[O_AUX+3]=ddx/nrm; G[O_AUX+4]=ddy/nrm; G[O_AUX+5]=ddz/nrm;
        }
        #pragma unroll
        for (int e=lane; e<64; e+=32){
            float t = (e==63) ? 1.0f : (float)e * (1.0f/63.0f);
            G[O_D + e] = 0.5f*(1.0f-t) + 4.0f*t;
        }
        __syncwarp();

        const float ox=G[O_AUX+0], oy=G[O_AUX+1], oz=G[O_AUX+2];
        const float dx=G[O_AUX+3], dy=G[O_AUX+4], dz=G[O_AUX+5];

        float c0[4], c1[4], b2v[4], w3v[4];
        #pragma unroll
        for (int u=0; u<4; u++){
            int j = lane + 32*u;
            c1[u] = dx*W1s[j] + dy*W1s[128+j] + dz*W1s[256+j];
            c0[u] = b1s[j] + ox*W1s[j] + oy*W1s[128+j] + oz*W1s[256+j];
            b2v[u]= b2s[j];
            w3v[u]= W3s[j];
        }
        const float b3v = b3p[0];

        // ---- coarse SDF ----
        for (int b=0;b<8;b++)
            sdf_batch(G, W2T, O_D, b*8, O_SDF, lane, c0,c1,b2v,w3v,b3v);

        // ---- hierarchical upsampling ----
        int n = 64;
        for (int it=0; it<4; it++){
            float s_i = 64.0f * (float)(1<<it);
            #pragma unroll
            for (int e=lane; e<128; e+=32){
                float val = 0.0f;
                if (e < n-1){
                    float psdf=G[O_SDF+e], nsdf=G[O_SDF+e+1], pz=G[O_D+e], nz=G[O_D+e+1];
                    float dot = (nsdf-psdf)/(nz-pz+1e-5f);
                    float pdot = 0.0f;
                    if (e > 0){
                        float ppsdf=G[O_SDF+e-1], ppz=G[O_D+e-1];
                        pdot = (psdf-ppsdf)/(pz-ppz+1e-5f);
                    }
                    float dc = fminf(fmaxf(fminf(pdot,dot),-10.0f),0.0f);
                    float mid = 0.5f*(psdf+nsdf), dist = nz-pz;
                    float pc = sigf((mid - dc*dist*0.5f)*s_i);
                    float nc = sigf((mid + dc*dist*0.5f)*s_i);
                    val = (pc-nc+1e-5f)/(pc+1e-5f);
                }
                G[O_WB+e] = val;
            }
            __syncwarp();

            // warp scan: w = a*T + 1e-5 ; cdf = cumsum(w)/sum
            {
                float4 av = *(const float4*)(G + O_WB + 4*lane);
                float a[4] = {av.x, av.y, av.z, av.w};
                float sh[4], Tl[4], wv4[4];
                #pragma unroll
                for (int r=0;r<4;r++){
                    int e = 4*lane + r;
                    sh[r] = (e < n-1) ? (1.0f - a[r] + 1e-10f) : 1.0f;
                }
                Tl[0]=1.0f; Tl[1]=sh[0]; Tl[2]=sh[0]*sh[1]; Tl[3]=Tl[2]*sh[2];
                float P = Tl[3]*sh[3];
                float v = P;
                #pragma unroll
                for (int o=1;o<32;o<<=1){
                    float t = __shfl_up_sync(FULL, v, o);
                    if (lane >= o) v *= t;
                }
                float exc = __shfl_up_sync(FULL, v, 1);
                if (lane == 0) exc = 1.0f;
                float lsum = 0.f;
                #pragma unroll
                for (int r=0;r<4;r++){
                    int e = 4*lane + r;
                    wv4[r] = (e < n-1) ? fmaf(a[r], exc*Tl[r], 1e-5f) : 0.0f;
                    lsum += wv4[r];
                }
                float va = lsum;
                #pragma unroll
                for (int o=1;o<32;o<<=1){
                    float t = __shfl_up_sync(FULL, va, o);
                    if (lane >= o) va += t;
                }
                float total = __shfl_sync(FULL, va, 31);
                float inv = 1.0f/total;
                float base = va - lsum;
                float run = 0.f;
                #pragma unroll
                for (int r=0;r<4;r++){
                    run += wv4[r];
                    G[O_CDF + 4*lane + 1 + r] = (base + run)*inv;
                }
                if (lane == 0) G[O_CDF] = 0.0f;
            }
            __syncwarp();

            if (lane < 16){
                float u = (lane==15) ? 1.0f : (float)lane * (1.0f/15.0f);
                int lo = 0, hi = n;
                #pragma unroll
                for (int s7=0; s7<7; s7++){
                    int mid = (lo+hi) >> 1;
                    if (G[O_CDF+mid] <= u) lo = mid+1; else hi = mid;
                }
                int ind = lo;
                int below = ind-1; if (below < 0) below = 0; if (below > n-1) below = n-1;
                int above = (ind < n-1) ? ind : n-1;
                float cb=G[O_CDF+below], ca=G[O_CDF+above];
                float bb=G[O_D+below],  ba=G[O_D+above];
                float den = ca-cb; if (den < 1e-5f) den = 1.0f;
                float tt = (u-cb)/den;
                G[O_DF+lane] = bb + tt*(ba-bb);
            }
            __syncwarp();

            sdf_batch(G, W2T, O_DF, 0, O_SF, lane, c0,c1,b2v,w3v,b3v);
            sdf_batch(G, W2T, O_DF, 8, O_SF, lane, c0,c1,b2v,w3v,b3v);

            // ---- parallel stable merge via ranks ----
            {
                float dv[4], sv[4]; int rk[4];
                #pragma unroll
                for (int m=0;m<4;m++){
                    int e = lane + 32*m;
                    rk[m] = -1;
                    if (e < n){
                        dv[m]=G[O_D+e]; sv[m]=G[O_SDF+e];
                        int lo=0, hi=16;
                        #pragma unroll
                        for (int s5=0;s5<5;s5++){
                            int mid=(lo+hi)>>1;
                            if (mid < 16 && G[O_DF+mid] < dv[m]) lo=mid+1; else hi=mid;
                        }
                        rk[m] = e + lo;
                    }
                }
                float bf=0.f, bsf=0.f; int rkf=-1;
                if (lane < 16){
                    bf=G[O_DF+lane]; bsf=G[O_SF+lane];
                    int lo=0, hi=n;
                    #pragma unroll
                    for (int s7=0;s7<7;s7++){
                        int mid=(lo+hi)>>1;
                        if (mid < n && G[O_D+mid] <= bf) lo=mid+1; else hi=mid;
                    }
                    rkf = lane + lo;
                }
                __syncwarp();
                #pragma unroll
                for (int m=0;m<4;m++){
                    if (rk[m] >= 0){ G[O_D+rk[m]]=dv[m]; G[O_SDF+rk[m]]=sv[m]; }
                }
                if (rkf >= 0){ G[O_D+rkf]=bf; G[O_SDF+rkf]=bsf; }
            }
            __syncwarp();
            n += 16;
        }

        // ---- final compositing (n==128) ----
        const float s = scp[0];
        #pragma unroll
        for (int e=lane; e<128; e+=32) G[O_CDF+e] = sigf(G[O_SDF+e]*s);
        #pragma unroll
        for (int e=lane; e<128; e+=32) G[O_DM+e] = (e<127) ? 0.5f*(G[O_D+e]+G[O_D+e+1]) : 0.0f;
        __syncwarp();
        #pragma unroll
        for (int e=lane; e<128; e+=32){
            float val = 0.0f;
            if (e < 127){
                float a = (G[O_CDF+e]-G[O_CDF+e+1]+1e-5f)/(G[O_CDF+e]+1e-5f);
                val = fminf(fmaxf(a,0.0f),1.0f);
            }
            G[O_WB+e] = val;
        }
        __syncwarp();

        float wv4[4], dm4[4];
        {
            float4 av = *(const float4*)(G + O_WB + 4*lane);
            float4 dmv= *(const float4*)(G + O_DM + 4*lane);
            float a[4] = {av.x, av.y, av.z, av.w};
            dm4[0]=dmv.x; dm4[1]=dmv.y; dm4[2]=dmv.z; dm4[3]=dmv.w;
            float sh[4], Tl[4];
            #pragma unroll
            for (int r=0;r<4;r++){
                int e = 4*lane + r;
                sh[r] = (e < 127) ? (1.0f - a[r] + 1e-10f) : 1.0f;
            }
            Tl[0]=1.0f; Tl[1]=sh[0]; Tl[2]=sh[0]*sh[1]; Tl[3]=Tl[2]*sh[2];
            float P = Tl[3]*sh[3];
            float v = P;
            #pragma unroll
            for (int o=1;o<32;o<<=1){
                float t = __shfl_up_sync(FULL, v, o);
                if (lane >= o) v *= t;
            }
            float exc = __shfl_up_sync(FULL, v, 1);
            if (lane == 0) exc = 1.0f;
            #pragma unroll
            for (int r=0;r<4;r++){
                int e = 4*lane + r;
                wv4[r] = (e < 127) ? a[r]*exc*Tl[r] : 0.0f;
            }
        }

        // ---- radiance: per-ray A0/A1 staging, flipped loop ----
        float* A0 = G + O_H1;
        float* A1 = G + O_H1 + 128;
        #pragma unroll
        for (int u=0; u<4; u++){
            int j = lane + 32*u;
            float c1r = dx*R1s[j] + dy*R1s[128+j] + dz*R1s[256+j];
            float c0r = r1s[j] + ox*R1s[j] + oy*R1s[128+j] + oz*R1s[256+j]
                      + dx*R1s[384+j] + dy*R1s[512+j] + dz*R1s[640+j];
            A0[j]=c0r; A1[j]=c1r;
        }
        __syncwarp();

        float t0[4]={0,0,0,0}, t1[4]={0,0,0,0}, t2[4]={0,0,0,0};
        #pragma unroll 2
        for (int k4=0; k4<32; k4++){
            float4 C0=*(const float4*)(A0+4*k4);
            float4 C1=*(const float4*)(A1+4*k4);
            float4 G0=*(const float4*)(F0+4*k4);
            float4 G1=*(const float4*)(F1+4*k4);
            float4 G2=*(const float4*)(F2+4*k4);
            const float c0k[4]={C0.x,C0.y,C0.z,C0.w};
            const float c1k[4]={C1.x,C1.y,C1.z,C1.w};
            const float f0k[4]={G0.x,G0.y,G0.z,G0.w};
            const float f1k[4]={G1.x,G1.y,G1.z,G1.w};
            const float f2k[4]={G2.x,G2.y,G2.z,G2.w};
            #pragma unroll
            for (int kk=0;kk<4;kk++){
                #pragma unroll
                for (int r=0;r<4;r++){
                    float h = fmaxf(fmaf(dm4[r], c1k[kk], c0k[kk]), 0.f);
                    t0[r] = fmaf(h, f0k[kk], t0[r]);
                    t1[r] = fmaf(h, f1k[kk], t1[r]);
                    t2[r] = fmaf(h, f2k[kk], t2[r]);
                }
            }
        }

        const float r2c0=r2s[0], r2c1=r2s[1], r2c2=r2s[2];
        float rgb0=0.f, rgb1=0.f, rgb2=0.f, dep=0.f, ac=0.f;
        #pragma unroll
        for (int r=0;r<4;r++){
            float wvv = wv4[r];
            rgb0 = fmaf(wvv, sigf(t0[r]+r2c0), rgb0);
            rgb1 = fmaf(wvv, sigf(t1[r]+r2c1), rgb1);
            rgb2 = fmaf(wvv, sigf(t2[r]+r2c2), rgb2);
            dep  = fmaf(wvv, dm4[r], dep);
            ac  += wvv;
        }
        #pragma unroll
        for (int o=16;o;o>>=1){
            rgb0 += __shfl_down_sync(FULL, rgb0, o);
            rgb1 += __shfl_down_sync(FULL, rgb1, o);
            rgb2 += __shfl_down_sync(FULL, rgb2, o);
            dep  += __shfl_down_sync(FULL, dep, o);
            ac   += __shfl_down_sync(FULL, ac, o);
        }
        if (lane == 0){
            out[ray*5+0]=rgb0;
            out[ray*5+1]=rgb1;
            out[ray*5+2]=rgb2;
            out[ray*5+3]=dep;
            out[ray*5+4]=ac;
        }
        __syncwarp();
    }
}

extern "C" void kernel_launch(void* const* d_in, const int* in_sizes, int n_in,
                              void* d_out, int out_size)
{
    const float* rays_o = (const float*)d_in[0];
    const float* rays_d = (const float*)d_in[1];
    const float* W1 = (const float*)d_in[2];
    const float* b1 = (const float*)d_in[3];
    const float* W2 = (const float*)d_in[4];
    const float* b2 = (const float*)d_in[5];
    const float* W3 = (const float*)d_in[6];
    const float* b3 = (const float*)d_in[7];
    const float* R1 = (const float*)d_in[8];
    const float* r1 = (const float*)d_in[9];
    const float* R2 = (const float*)d_in[10];
    const float* r2 = (const float*)d_in[11];
    const float* sv = (const float*)d_in[12];
    float* out = (float*)d_out;

    cudaFuncSetAttribute(neus_kernel, cudaFuncAttributeMaxDynamicSharedMemorySize, SMEM_BYTES);
    neus_kernel<<<NBLK, TPB, SMEM_BYTES>>>(rays_o,rays_d,W1,b1,W2,b2,W3,b3,R1,r1,R2,r2,sv,out);
}